// round 12
// baseline (speedup 1.0000x reference)
#include <cuda_runtime.h>
#include <cuda_fp16.h>
#include <cstdint>

#define NN 200000
#define NE 400000
#define HS 128
#define ROW_TILES 1563            // ceil(200000/128)
#define NPAD (ROW_TILES * 128)    // 200064 padded rows

#define TSZ 32768                 // bytes per swizzled [128x128] fp16 tile
#define SMEM_MMA (3 * TSZ)        // A hi/lo + B single buffer = 98304 B

// ---------------- scratch (device globals; no allocs allowed) ----------------
// NOTE: never passed as kernel args from host (host shadow + ATS trap);
// all resolution happens inside device code via `sel`.
__device__ float g_xall[(size_t)NN * 384];   // x@w_iou^T + b_iou   [N,384] = i|o|u (fp32)
__device__ __align__(16) __half g_xf16[(size_t)NPAD * HS];  // x@w_f^T + b_f (fp16)
__device__ __align__(16) __half g_hu16[(size_t)NPAD * HS];  // h_child @ u_f^T (fp16)
__device__ float g_hsum[(size_t)NN * HS];    // segsum(h_child[src])    [N,128]
__device__ float g_fcsum[(size_t)NN * HS];   // segsum(f*c_child[src])  [N,128]
// pre-split fp16 A operands: A = hi + lo (22-bit effective mantissa)
__device__ __align__(16) __half g_xhi[(size_t)NPAD * HS];
__device__ __align__(16) __half g_xlo[(size_t)NPAD * HS];
__device__ __align__(16) __half g_hhi[(size_t)NPAD * HS];
__device__ __align__(16) __half g_hlo[(size_t)NPAD * HS];
__device__ __align__(16) __half g_shi[(size_t)NPAD * HS];
__device__ __align__(16) __half g_slo[(size_t)NPAD * HS];
// packed fp16 weights (hi only), 8 tiles of [128 n][128 k] row-major:
// tiles 0-3: [w_iou;w_f] (512 rows: 0=i,1=o,2=u,3=f), 4-6: u_iou (4=i,5=o,6=u), 7: u_f
__device__ __align__(16) __half g_Bhi[8 * 16384];
__device__ __align__(16) float g_bias[512];

__device__ __forceinline__ float sigmoidf(float v) { return 1.0f / (1.0f + __expf(-v)); }

__device__ __forceinline__ uint32_t smem_u32(const void* p) {
    uint32_t a;
    asm("{ .reg .u64 t; cvta.to.shared.u64 t, %1; cvt.u32.u64 %0, t; }" : "=r"(a) : "l"(p));
    return a;
}

__device__ __forceinline__ void ldsm4(uint32_t* r, uint32_t addr) {
    asm volatile("ldmatrix.sync.aligned.m8n8.x4.shared.b16 {%0,%1,%2,%3}, [%4];"
                 : "=r"(r[0]), "=r"(r[1]), "=r"(r[2]), "=r"(r[3]) : "r"(addr));
}

__device__ __forceinline__ void mma16816(float* c, const uint32_t* a, uint32_t b0, uint32_t b1) {
    asm volatile(
        "mma.sync.aligned.m16n8k16.row.col.f32.f16.f16.f32 "
        "{%0,%1,%2,%3}, {%4,%5,%6,%7}, {%8,%9}, {%0,%1,%2,%3};"
        : "+f"(c[0]), "+f"(c[1]), "+f"(c[2]), "+f"(c[3])
        : "r"(a[0]), "r"(a[1]), "r"(a[2]), "r"(a[3]), "r"(b0), "r"(b1));
}

__device__ __forceinline__ void cp16(uint32_t dst, const void* src) {
    asm volatile("cp.async.cg.shared.global [%0], [%1], 16;" :: "r"(dst), "l"(src));
}
__device__ __forceinline__ void cp_commit() {
    asm volatile("cp.async.commit_group;");
}
template <int N>
__device__ __forceinline__ void cp_wait() {
    asm volatile("cp.async.wait_group %0;" :: "n"(N));
}

__device__ __forceinline__ uint32_t pack2h(__half lo, __half hi) {
    return (uint32_t)__half_as_ushort(lo) | ((uint32_t)__half_as_ushort(hi) << 16);
}

// ---------------- split fp32 -> fp16 hi/lo (4 elems per thread) ----------------
// sel 0: src=ext (x)       -> g_xhi/g_xlo   (+ zero g_hsum/g_fcsum)
// sel 1: src=ext (h_child) -> g_hhi/g_hlo
// sel 2: src=g_hsum        -> g_shi/g_slo
__global__ void k_split(const float* __restrict__ ext, int sel) {
    const int total4 = NN * HS / 4;
    int i = blockIdx.x * blockDim.x + threadIdx.x;
    if (i >= total4) return;
    const float* src = (sel == 2) ? g_hsum : ext;
    __half* hi = (sel == 0) ? g_xhi : (sel == 1) ? g_hhi : g_shi;
    __half* lo = (sel == 0) ? g_xlo : (sel == 1) ? g_hlo : g_slo;
    if (sel == 0) {
        float4 z = make_float4(0.f, 0.f, 0.f, 0.f);
        reinterpret_cast<float4*>(g_hsum)[i] = z;
        reinterpret_cast<float4*>(g_fcsum)[i] = z;
    }
    float4 v = reinterpret_cast<const float4*>(src)[i];
    float f[4] = {v.x, v.y, v.z, v.w};
    uint32_t hp[2], lp[2];
#pragma unroll
    for (int p = 0; p < 2; p++) {
        __half h0 = __float2half_rn(f[2 * p]);
        __half h1 = __float2half_rn(f[2 * p + 1]);
        __half l0 = __float2half_rn(f[2 * p] - __half2float(h0));
        __half l1 = __float2half_rn(f[2 * p + 1] - __half2float(h1));
        hp[p] = pack2h(h0, h1);
        lp[p] = pack2h(l0, l1);
    }
    reinterpret_cast<uint2*>(hi)[i] = make_uint2(hp[0], hp[1]);
    reinterpret_cast<uint2*>(lo)[i] = make_uint2(lp[0], lp[1]);
}

// ---------------- pack weights: fp32 -> fp16, row-major [n][k] tiles ----------------
__global__ void k_prep(const float* __restrict__ w_iou, const float* __restrict__ w_f,
                       const float* __restrict__ u_iou, const float* __restrict__ u_f,
                       const float* __restrict__ b_iou, const float* __restrict__ b_f) {
    int i = blockIdx.x * blockDim.x + threadIdx.x;
    if (i < 512) g_bias[i] = (i < 384) ? b_iou[i] : b_f[i - 384];
    if (i >= 131072) return;
    int n, k, tile;
    float val;
    if (i < 65536) {                       // [w_iou ; w_f], 512 rows
        n = i >> 7; k = i & 127;
        tile = n >> 7;
        val = (n < 384) ? w_iou[n * 128 + k] : w_f[(n - 384) * 128 + k];
    } else if (i < 65536 + 49152) {        // u_iou, 384 rows
        int j = i - 65536;
        n = j >> 7; k = j & 127;
        tile = 4 + (n >> 7);
        val = u_iou[n * 128 + k];
    } else {                               // u_f, 128 rows
        int j = i - 114688;
        n = j >> 7; k = j & 127;
        tile = 7;
        val = u_f[n * 128 + k];
    }
    g_Bhi[tile * 16384 + (n & 127) * 128 + k] = __float2half_rn(val);
}

// swizzled byte offset of 16B chunk (r, c) in a [128 rows x 16 chunks] tile
__device__ __forceinline__ uint32_t sw_chunk(int r, int c) {
    return (uint32_t)(r * 256 + ((c ^ (r & 7)) << 4));
}

// copy one [128][128] fp16 tile, global row-major -> swizzled smem, via cp.async
__device__ __forceinline__ void copy_tile(uint32_t sdst, const __half* gsrc, int tid) {
#pragma unroll
    for (int it = 0; it < 8; it++) {
        int j = tid + it * 256;        // 2048 16B chunks
        int r = j >> 4, c = j & 15;
        cp16(sdst + sw_chunk(r, c), gsrc + r * 128 + c * 8);
    }
}

// shared 2-term MMA inner loop (D = Ahi*B + Alo*B); per-lane smem bases precomputed
struct LaneMap {
    uint32_t aBase0, aBase1, bBase;
    uint32_t c0a, rma, c0b, rmb;
};
__device__ __forceinline__ void mma_inner(float acc[2][8][4], const LaneMap& L, uint32_t bOff) {
#pragma unroll
    for (int i = 0; i < 2; i++)
#pragma unroll
        for (int j = 0; j < 8; j++)
#pragma unroll
            for (int q = 0; q < 4; q++) acc[i][j][q] = 0.f;
#pragma unroll
    for (int kb = 0; kb < 8; kb++) {
        const uint32_t ca = (uint32_t)(((L.c0a + 2 * kb) ^ L.rma) << 4);
        const uint32_t cb = (uint32_t)(((L.c0b + 2 * kb) ^ L.rmb) << 4);
        uint32_t aH[2][4], aL[2][4];
        ldsm4(aH[0], L.aBase0 + ca);
        ldsm4(aH[1], L.aBase1 + ca);
        ldsm4(aL[0], L.aBase0 + TSZ + ca);
        ldsm4(aL[1], L.aBase1 + TSZ + ca);
        uint32_t b[4][4];
#pragma unroll
        for (int p = 0; p < 4; p++)
            ldsm4(b[p], L.bBase + bOff + p * 16 * 256 + cb);
#pragma unroll
        for (int i = 0; i < 2; i++)
#pragma unroll
            for (int j = 0; j < 8; j++) {
                uint32_t b0 = b[j >> 1][(j & 1) * 2], b1 = b[j >> 1][(j & 1) * 2 + 1];
                mma16816(acc[i][j], aH[i], b0, b1);
                mma16816(acc[i][j], aL[i], b0, b1);
            }
    }
}

__device__ __forceinline__ LaneMap make_lanemap(uint32_t sA, uint32_t sB, int lane, int wid) {
    LaneMap L;
    const int wr = wid & 3, wcol = wid >> 2;
    const int aRow = wr * 32 + (lane & 15);
    const int gg = lane >> 3;
    const int bRow = wcol * 64 + (gg >> 1) * 8 + (lane & 7);
    L.c0a = (uint32_t)(lane >> 4);
    L.rma = (uint32_t)(aRow & 7);
    L.c0b = (uint32_t)(gg & 1);
    L.rmb = (uint32_t)(bRow & 7);
    L.aBase0 = sA + (uint32_t)aRow * 256;
    L.aBase1 = L.aBase0 + 16 * 256;
    L.bBase = sB + (uint32_t)bRow * 256;
    return L;
}

// ============================================================================
// k_mma: sel 0: x -> g_xall (i,o,u tiles fp32 + f tile fp16 -> g_xf16), +bias.
//        sel 1: h_child -> g_hu16 (fp16).
// 2 CTAs/SM (96KB smem, 128 regs).
// ============================================================================
__global__ void __launch_bounds__(256, 2) k_mma(int sel) {
    const __half* Ahi = (sel == 0) ? g_xhi : g_hhi;
    const __half* Alo = (sel == 0) ? g_xlo : g_hlo;
    const int first  = (sel == 0) ? 0 : 7;
    const int ntiles = (sel == 0) ? 4 : 1;

    extern __shared__ __half sm[];
    const int tid = threadIdx.x;
    const int lane = tid & 31, wid = tid >> 5;
    const int brow = blockIdx.x * 128;

    const uint32_t sA = smem_u32(sm);
    const uint32_t sB = sA + 2 * TSZ;

    copy_tile(sA, Ahi + (size_t)brow * 128, tid);
    copy_tile(sA + TSZ, Alo + (size_t)brow * 128, tid);
    copy_tile(sB, g_Bhi + (size_t)first * 16384, tid);
    cp_commit();

    const LaneMap L = make_lanemap(sA, sB, lane, wid);
    const int wr = wid & 3, wcol = wid >> 2;

    for (int t = 0; t < ntiles; t++) {
        cp_wait<0>();
        __syncthreads();

        float acc[2][8][4];
        mma_inner(acc, L, 0);

        __syncthreads();
        if (t + 1 < ntiles) {
            copy_tile(sB, g_Bhi + (size_t)(first + t + 1) * 16384, tid);
            cp_commit();
        }

        const bool ftile = (sel == 0) && (t == 3);
        const int colb = (sel == 0 && t < 3) ? (t * 128 + wcol * 64) : (wcol * 64);
        const int biasb = (sel == 0) ? ((t < 3) ? t * 128 : 384) + wcol * 64 : 0;
#pragma unroll
        for (int i = 0; i < 2; i++) {
            int row0 = brow + wr * 32 + i * 16 + (lane >> 2);
            int row1 = row0 + 8;
#pragma unroll
            for (int j = 0; j < 8; j++) {
                int cj = j * 8 + (lane & 3) * 2;
                float bx = 0.f, by = 0.f;
                if (sel == 0) { bx = g_bias[biasb + cj]; by = g_bias[biasb + cj + 1]; }
#pragma unroll
                for (int h2 = 0; h2 < 2; h2++) {
                    int grow = h2 ? row1 : row0;
                    if (grow >= NN) continue;
                    float v0 = acc[i][j][h2 * 2] + bx;
                    float v1 = acc[i][j][h2 * 2 + 1] + by;
                    if (sel == 1) {
                        *reinterpret_cast<__half2*>(g_hu16 + (size_t)grow * HS + colb + cj) =
                            __floats2half2_rn(v0, v1);
                    } else if (ftile) {
                        *reinterpret_cast<__half2*>(g_xf16 + (size_t)grow * HS + colb + cj) =
                            __floats2half2_rn(v0, v1);
                    } else {
                        *reinterpret_cast<float2*>(g_xall + (size_t)grow * 384 + colb + cj) =
                            make_float2(v0, v1);
                    }
                }
            }
        }
    }
}

// ============================================================================
// k_mma3: hsum GEMM fused with full node update. All 3 gate tiles map to the
// SAME output columns, so sigma(i) / tanh(c) stage in 32 packed half2 REGISTERS.
// Gate order: t=0 i (btile 4, xall off 0), t=1 u (btile 6, off 256),
//             t=2 o (btile 5, off 128). Writes h, c directly to out.
// ============================================================================
__global__ void __launch_bounds__(256) k_mma3(float* __restrict__ out) {
    extern __shared__ __half sm[];
    const int tid = threadIdx.x;
    const int lane = tid & 31, wid = tid >> 5;
    const int brow = blockIdx.x * 128;

    const uint32_t sA = smem_u32(sm);
    const uint32_t sB = sA + 2 * TSZ;

    const int BT[3]   = {4, 6, 5};
    const int XOFF[3] = {0, 256, 128};

    copy_tile(sA, g_shi + (size_t)brow * 128, tid);
    copy_tile(sA + TSZ, g_slo + (size_t)brow * 128, tid);
    copy_tile(sB, g_Bhi + (size_t)BT[0] * 16384, tid);
    cp_commit();

    const LaneMap L = make_lanemap(sA, sB, lane, wid);
    const int wr = wid & 3, wcol = wid >> 2;

    __half2 stage[2][8][2];   // sigma(i) after t=0; tanh(c) after t=1

    for (int t = 0; t < 3; t++) {
        cp_wait<0>();
        __syncthreads();

        float acc[2][8][4];
        mma_inner(acc, L, 0);

        __syncthreads();
        if (t + 1 < 3) {
            copy_tile(sB, g_Bhi + (size_t)BT[t + 1] * 16384, tid);
            cp_commit();
        }

        const int xoff = XOFF[t];
        const int colb = wcol * 64;
#pragma unroll
        for (int i = 0; i < 2; i++) {
            int row0 = brow + wr * 32 + i * 16 + (lane >> 2);
#pragma unroll
            for (int j = 0; j < 8; j++) {
                int col = colb + j * 8 + (lane & 3) * 2;
#pragma unroll
                for (int h2 = 0; h2 < 2; h2++) {
                    int grow = row0 + h2 * 8;
                    if (grow >= NN) continue;
                    float2 xa = *reinterpret_cast<const float2*>(
                        g_xall + (size_t)grow * 384 + xoff + col);
                    float p0 = acc[i][j][h2 * 2] + xa.x;
                    float p1 = acc[i][j][h2 * 2 + 1] + xa.y;
                    if (t == 0) {                 // i gate
                        stage[i][j][h2] = __floats2half2_rn(sigmoidf(p0), sigmoidf(p1));
                    } else if (t == 1) {          // u gate -> c
                        float2 fc = *reinterpret_cast<const float2*>(
                            g_fcsum + (size_t)grow * HS + col);
                        float2 si = __half22float2(stage[i][j][h2]);
                        float c0 = si.x * tanhf(p0) + fc.x;
                        float c1 = si.y * tanhf(p1) + fc.y;
                        *reinterpret_cast<float2*>(out + (size_t)NN * HS +
                                                   (size_t)grow * HS + col) =
                            make_float2(c0, c1);
                        stage[i][j][h2] = __floats2half2_rn(tanhf(c0), tanhf(c1));
                    } else {                      // o gate -> h
                        float2 tc = __half22float2(stage[i][j][h2]);
                        float h0 = sigmoidf(p0) * tc.x;
                        float h1 = sigmoidf(p1) * tc.y;
                        *reinterpret_cast<float2*>(out + (size_t)grow * HS + col) =
                            make_float2(h0, h1);
                    }
                }
            }
        }
    }
}

// ---------------- edge pass: one warp per edge, fp16 hu/xf gathers ----------------
__global__ void k_edge(const float* __restrict__ h_child, const float* __restrict__ c_child,
                       const int* __restrict__ esrc, const int* __restrict__ edst) {
    int idx = blockIdx.x * blockDim.x + threadIdx.x;
    int e = idx >> 5;
    int q = idx & 31;
    if (e >= NE) return;
    int s = esrc[e];
    int d = edst[e];
    float4 h4 = reinterpret_cast<const float4*>(h_child + (size_t)s * HS)[q];
    float4 c4 = reinterpret_cast<const float4*>(c_child + (size_t)s * HS)[q];
    const __half2* hu2 = reinterpret_cast<const __half2*>(g_hu16 + (size_t)s * HS + q * 4);
    const __half2* xf2 = reinterpret_cast<const __half2*>(g_xf16 + (size_t)d * HS + q * 4);
    float2 huA = __half22float2(hu2[0]), huB = __half22float2(hu2[1]);
    float2 xfA = __half22float2(xf2[0]), xfB = __half22float2(xf2[1]);
    float* hs = g_hsum + (size_t)d * HS + q * 4;
    float* fc = g_fcsum + (size_t)d * HS + q * 4;
    atomicAdd(hs + 0, h4.x); atomicAdd(hs + 1, h4.y);
    atomicAdd(hs + 2, h4.z); atomicAdd(hs + 3, h4.w);
    atomicAdd(fc + 0, sigmoidf(xfA.x + huA.x) * c4.x);
    atomicAdd(fc + 1, sigmoidf(xfA.y + huA.y) * c4.y);
    atomicAdd(fc + 2, sigmoidf(xfB.x + huB.x) * c4.z);
    atomicAdd(fc + 3, sigmoidf(xfB.y + huB.y) * c4.w);
}

// ============================================================================
extern "C" void kernel_launch(void* const* d_in, const int* in_sizes, int n_in,
                              void* d_out, int out_size) {
    const float* x       = (const float*)d_in[0];
    const float* h_child = (const float*)d_in[1];
    const float* c_child = (const float*)d_in[2];
    const float* w_iou   = (const float*)d_in[3];
    const float* b_iou   = (const float*)d_in[4];
    const float* w_f     = (const float*)d_in[5];
    const float* b_f     = (const float*)d_in[6];
    const float* u_iou   = (const float*)d_in[7];
    const float* u_f     = (const float*)d_in[8];
    const int*   esrc    = (const int*)d_in[9];
    const int*   edst    = (const int*)d_in[10];
    float* out = (float*)d_out;

    static bool configured = false;
    if (!configured) {
        cudaFuncSetAttribute(k_mma, cudaFuncAttributeMaxDynamicSharedMemorySize, SMEM_MMA);
        cudaFuncSetAttribute(k_mma3, cudaFuncAttributeMaxDynamicSharedMemorySize, SMEM_MMA);
        configured = true;
    }

    const int total4 = NN * HS / 4;
    const int sgrid = (total4 + 255) / 256;

    k_prep<<<131072 / 256, 256>>>(w_iou, w_f, u_iou, u_f, b_iou, b_f);
    k_split<<<sgrid, 256>>>(x, 0);            // also zeroes g_hsum/g_fcsum
    k_split<<<sgrid, 256>>>(h_child, 1);
    k_mma<<<ROW_TILES, 256, SMEM_MMA>>>(0);   // x -> g_xall (i|o|u) + g_xf16 (f)
    k_mma<<<ROW_TILES, 256, SMEM_MMA>>>(1);   // h_child -> g_hu16
    k_edge<<<(NE * 32) / 256, 256>>>(h_child, c_child, esrc, edst);
    k_split<<<sgrid, 256>>>(nullptr, 2);      // g_hsum -> g_shi/g_slo
    k_mma3<<<ROW_TILES, 256, SMEM_MMA>>>(out); // fused uh GEMM + node update
}

// round 13
// speedup vs baseline: 1.3018x; 1.3018x over previous
#include <cuda_runtime.h>
#include <cuda_fp16.h>
#include <cstdint>

#define NN 200000
#define NE 400000
#define HS 128
#define ROW_TILES 1563            // ceil(200000/128)
#define NPAD (ROW_TILES * 128)    // 200064 padded rows

#define TSZ 32768                 // bytes per swizzled [128x128] fp16 tile
#define SMEM_MMA (3 * TSZ)        // A hi/lo + B single buffer = 98304 B

// ---------------- scratch (device globals; no allocs allowed) ----------------
// NOTE: never passed as kernel args from host (host shadow + ATS trap);
// all resolution happens inside device code via `sel`.
__device__ float g_xall[(size_t)NN * 384];   // x@w_iou^T + b_iou   [N,384] = i|o|u (fp32)
__device__ float g_uhsum[(size_t)NN * 384];  // hsum @ u_iou^T      [N,384] (fp32)
__device__ __align__(16) __half g_xf16[(size_t)NPAD * HS];  // x@w_f^T + b_f (fp16)
__device__ __align__(16) __half g_hu16[(size_t)NPAD * HS];  // h_child @ u_f^T (fp16)
__device__ float g_hsum[(size_t)NN * HS];    // segsum(h_child[src])    [N,128]
__device__ float g_fcsum[(size_t)NN * HS];   // segsum(f*c_child[src])  [N,128]
// pre-split fp16 A operands: A = hi + lo (22-bit effective mantissa)
__device__ __align__(16) __half g_xhi[(size_t)NPAD * HS];
__device__ __align__(16) __half g_xlo[(size_t)NPAD * HS];
__device__ __align__(16) __half g_hhi[(size_t)NPAD * HS];
__device__ __align__(16) __half g_hlo[(size_t)NPAD * HS];
__device__ __align__(16) __half g_shi[(size_t)NPAD * HS];
__device__ __align__(16) __half g_slo[(size_t)NPAD * HS];
// packed fp16 weights (hi only), 8 tiles of [128 n][128 k] row-major:
// tiles 0-3: [w_iou;w_f] (512 rows: 0=i,1=o,2=u,3=f), 4-6: u_iou (4=i,5=o,6=u), 7: u_f
__device__ __align__(16) __half g_Bhi[8 * 16384];
__device__ __align__(16) float g_bias[512];

__device__ __forceinline__ float sigmoidf(float v) { return 1.0f / (1.0f + __expf(-v)); }

__device__ __forceinline__ uint32_t smem_u32(const void* p) {
    uint32_t a;
    asm("{ .reg .u64 t; cvta.to.shared.u64 t, %1; cvt.u32.u64 %0, t; }" : "=r"(a) : "l"(p));
    return a;
}

__device__ __forceinline__ void ldsm4(uint32_t* r, uint32_t addr) {
    asm volatile("ldmatrix.sync.aligned.m8n8.x4.shared.b16 {%0,%1,%2,%3}, [%4];"
                 : "=r"(r[0]), "=r"(r[1]), "=r"(r[2]), "=r"(r[3]) : "r"(addr));
}

__device__ __forceinline__ void mma16816(float* c, const uint32_t* a, uint32_t b0, uint32_t b1) {
    asm volatile(
        "mma.sync.aligned.m16n8k16.row.col.f32.f16.f16.f32 "
        "{%0,%1,%2,%3}, {%4,%5,%6,%7}, {%8,%9}, {%0,%1,%2,%3};"
        : "+f"(c[0]), "+f"(c[1]), "+f"(c[2]), "+f"(c[3])
        : "r"(a[0]), "r"(a[1]), "r"(a[2]), "r"(a[3]), "r"(b0), "r"(b1));
}

__device__ __forceinline__ void cp16(uint32_t dst, const void* src) {
    asm volatile("cp.async.cg.shared.global [%0], [%1], 16;" :: "r"(dst), "l"(src));
}
__device__ __forceinline__ void cp_commit() {
    asm volatile("cp.async.commit_group;");
}
template <int N>
__device__ __forceinline__ void cp_wait() {
    asm volatile("cp.async.wait_group %0;" :: "n"(N));
}

__device__ __forceinline__ uint32_t pack2h(__half lo, __half hi) {
    return (uint32_t)__half_as_ushort(lo) | ((uint32_t)__half_as_ushort(hi) << 16);
}

// ---------------- split fp32 -> fp16 hi/lo (4 elems per thread) ----------------
// sel 0: src=ext (x)       -> g_xhi/g_xlo   (+ zero g_hsum/g_fcsum)
// sel 1: src=ext (h_child) -> g_hhi/g_hlo
// sel 2: src=g_hsum        -> g_shi/g_slo
__global__ void k_split(const float* __restrict__ ext, int sel) {
    const int total4 = NN * HS / 4;
    int i = blockIdx.x * blockDim.x + threadIdx.x;
    if (i >= total4) return;
    const float* src = (sel == 2) ? g_hsum : ext;
    __half* hi = (sel == 0) ? g_xhi : (sel == 1) ? g_hhi : g_shi;
    __half* lo = (sel == 0) ? g_xlo : (sel == 1) ? g_hlo : g_slo;
    if (sel == 0) {
        float4 z = make_float4(0.f, 0.f, 0.f, 0.f);
        reinterpret_cast<float4*>(g_hsum)[i] = z;
        reinterpret_cast<float4*>(g_fcsum)[i] = z;
    }
    float4 v = reinterpret_cast<const float4*>(src)[i];
    float f[4] = {v.x, v.y, v.z, v.w};
    uint32_t hp[2], lp[2];
#pragma unroll
    for (int p = 0; p < 2; p++) {
        __half h0 = __float2half_rn(f[2 * p]);
        __half h1 = __float2half_rn(f[2 * p + 1]);
        __half l0 = __float2half_rn(f[2 * p] - __half2float(h0));
        __half l1 = __float2half_rn(f[2 * p + 1] - __half2float(h1));
        hp[p] = pack2h(h0, h1);
        lp[p] = pack2h(l0, l1);
    }
    reinterpret_cast<uint2*>(hi)[i] = make_uint2(hp[0], hp[1]);
    reinterpret_cast<uint2*>(lo)[i] = make_uint2(lp[0], lp[1]);
}

// ---------------- pack weights: fp32 -> fp16, row-major [n][k] tiles ----------------
__global__ void k_prep(const float* __restrict__ w_iou, const float* __restrict__ w_f,
                       const float* __restrict__ u_iou, const float* __restrict__ u_f,
                       const float* __restrict__ b_iou, const float* __restrict__ b_f) {
    int i = blockIdx.x * blockDim.x + threadIdx.x;
    if (i < 512) g_bias[i] = (i < 384) ? b_iou[i] : b_f[i - 384];
    if (i >= 131072) return;
    int n, k, tile;
    float val;
    if (i < 65536) {                       // [w_iou ; w_f], 512 rows
        n = i >> 7; k = i & 127;
        tile = n >> 7;
        val = (n < 384) ? w_iou[n * 128 + k] : w_f[(n - 384) * 128 + k];
    } else if (i < 65536 + 49152) {        // u_iou, 384 rows
        int j = i - 65536;
        n = j >> 7; k = j & 127;
        tile = 4 + (n >> 7);
        val = u_iou[n * 128 + k];
    } else {                               // u_f, 128 rows
        int j = i - 114688;
        n = j >> 7; k = j & 127;
        tile = 7;
        val = u_f[n * 128 + k];
    }
    g_Bhi[tile * 16384 + (n & 127) * 128 + k] = __float2half_rn(val);
}

// swizzled byte offset of 16B chunk (r, c) in a [128 rows x 16 chunks] tile
__device__ __forceinline__ uint32_t sw_chunk(int r, int c) {
    return (uint32_t)(r * 256 + ((c ^ (r & 7)) << 4));
}

// copy one [128][128] fp16 tile, global row-major -> swizzled smem, via cp.async
__device__ __forceinline__ void copy_tile(uint32_t sdst, const __half* gsrc, int tid) {
#pragma unroll
    for (int it = 0; it < 8; it++) {
        int j = tid + it * 256;        // 2048 16B chunks
        int r = j >> 4, c = j & 15;
        cp16(sdst + sw_chunk(r, c), gsrc + r * 128 + c * 8);
    }
}

// ============================================================================
// fp16 mma.sync GEMM, 2-term split: D = Ahi*Bhi + Alo*Bhi.
// Swizzled 32KB tiles; A hi/lo + single B = 96KB -> 2 CTAs/SM.
// 256 threads, warp grid 4x2, warp tile 32x64 (R11-proven core).
// sel 0: x -> g_xall (i,o,u fp32) + g_xf16 (f, fp16), +bias
// sel 1: h_child -> g_hu16 (fp16)
// sel 2: hsum -> g_uhsum (fp32, 3 tiles)
// ============================================================================
__global__ void __launch_bounds__(256, 2) k_mma(int sel) {
    const __half* Ahi = (sel == 0) ? g_xhi : (sel == 1) ? g_hhi : g_shi;
    const __half* Alo = (sel == 0) ? g_xlo : (sel == 1) ? g_hlo : g_slo;
    const int first  = (sel == 0) ? 0 : (sel == 1) ? 7 : 4;
    const int ntiles = (sel == 0) ? 4 : (sel == 1) ? 1 : 3;

    extern __shared__ __half sm[];
    const int tid = threadIdx.x;
    const int lane = tid & 31, wid = tid >> 5;
    const int brow = blockIdx.x * 128;

    const uint32_t sA = smem_u32(sm);            // A hi; lo at +TSZ
    const uint32_t sB = sA + 2 * TSZ;            // single B buffer

    copy_tile(sA, Ahi + (size_t)brow * 128, tid);
    copy_tile(sA + TSZ, Alo + (size_t)brow * 128, tid);
    copy_tile(sB, g_Bhi + (size_t)first * 16384, tid);
    cp_commit();

    // ---- warp tiling: 4x2 warps, each 32 rows x 64 cols ----
    const int wr = wid & 3;
    const int wcol = wid >> 2;
    const int aRow = wr * 32 + (lane & 15);
    const int c0a  = lane >> 4;
    const int rma  = aRow & 7;
    const int gg   = lane >> 3;
    const int bRow = wcol * 64 + (gg >> 1) * 8 + (lane & 7);
    const int c0b  = gg & 1;
    const int rmb  = bRow & 7;

    const uint32_t aBase0 = sA + (uint32_t)aRow * 256;
    const uint32_t aBase1 = aBase0 + 16 * 256;
    const uint32_t bBase  = sB + (uint32_t)bRow * 256;

    for (int t = 0; t < ntiles; t++) {
        cp_wait<0>();
        __syncthreads();

        float acc[2][8][4];
#pragma unroll
        for (int i = 0; i < 2; i++)
#pragma unroll
            for (int j = 0; j < 8; j++)
#pragma unroll
                for (int q = 0; q < 4; q++) acc[i][j][q] = 0.f;

#pragma unroll
        for (int kb = 0; kb < 8; kb++) {
            const uint32_t ca = (uint32_t)(((c0a + 2 * kb) ^ rma) << 4);
            const uint32_t cb = (uint32_t)(((c0b + 2 * kb) ^ rmb) << 4);
            uint32_t aH[2][4], aL[2][4];
            ldsm4(aH[0], aBase0 + ca);
            ldsm4(aH[1], aBase1 + ca);
            ldsm4(aL[0], aBase0 + TSZ + ca);
            ldsm4(aL[1], aBase1 + TSZ + ca);
            uint32_t b[4][4];
#pragma unroll
            for (int p = 0; p < 4; p++)
                ldsm4(b[p], bBase + p * 16 * 256 + cb);
#pragma unroll
            for (int i = 0; i < 2; i++)
#pragma unroll
                for (int j = 0; j < 8; j++) {
                    uint32_t b0 = b[j >> 1][(j & 1) * 2], b1 = b[j >> 1][(j & 1) * 2 + 1];
                    mma16816(acc[i][j], aH[i], b0, b1);
                    mma16816(acc[i][j], aL[i], b0, b1);
                }
        }

        __syncthreads();
        if (t + 1 < ntiles) {                  // overlap next-B load with epilogue
            copy_tile(sB, g_Bhi + (size_t)(first + t + 1) * 16384, tid);
            cp_commit();
        }

        // ---- epilogue for this column tile ----
        const bool ftile = (sel == 0) && (t == 3);
        const int colb = ((sel == 0 && t < 3) || sel == 2) ? (t * 128 + wcol * 64)
                                                           : (wcol * 64);
        const int biasb = (sel == 0) ? (((t < 3) ? t * 128 : 384) + wcol * 64) : 0;
#pragma unroll
        for (int i = 0; i < 2; i++) {
            int row0 = brow + wr * 32 + i * 16 + (lane >> 2);
            int row1 = row0 + 8;
#pragma unroll
            for (int j = 0; j < 8; j++) {
                int cj = j * 8 + (lane & 3) * 2;
                float bx = 0.f, by = 0.f;
                if (sel == 0) { bx = g_bias[biasb + cj]; by = g_bias[biasb + cj + 1]; }
#pragma unroll
                for (int h2 = 0; h2 < 2; h2++) {
                    int grow = h2 ? row1 : row0;
                    if (grow >= NN) continue;
                    float v0 = acc[i][j][h2 * 2] + bx;
                    float v1 = acc[i][j][h2 * 2 + 1] + by;
                    if (sel == 1) {
                        *reinterpret_cast<__half2*>(g_hu16 + (size_t)grow * HS + colb + cj) =
                            __floats2half2_rn(v0, v1);
                    } else if (ftile) {
                        *reinterpret_cast<__half2*>(g_xf16 + (size_t)grow * HS + (wcol * 64) + cj) =
                            __floats2half2_rn(v0, v1);
                    } else if (sel == 0) {
                        *reinterpret_cast<float2*>(g_xall + (size_t)grow * 384 + colb + cj) =
                            make_float2(v0, v1);
                    } else {
                        *reinterpret_cast<float2*>(g_uhsum + (size_t)grow * 384 + colb + cj) =
                            make_float2(v0, v1);
                    }
                }
            }
        }
    }
}

// ---------------- edge pass: one warp per edge, fp16 hu/xf gathers ----------------
__global__ void k_edge(const float* __restrict__ h_child, const float* __restrict__ c_child,
                       const int* __restrict__ esrc, const int* __restrict__ edst) {
    int idx = blockIdx.x * blockDim.x + threadIdx.x;
    int e = idx >> 5;
    int q = idx & 31;
    if (e >= NE) return;
    int s = esrc[e];
    int d = edst[e];
    float4 h4 = reinterpret_cast<const float4*>(h_child + (size_t)s * HS)[q];
    float4 c4 = reinterpret_cast<const float4*>(c_child + (size_t)s * HS)[q];
    const __half2* hu2 = reinterpret_cast<const __half2*>(g_hu16 + (size_t)s * HS + q * 4);
    const __half2* xf2 = reinterpret_cast<const __half2*>(g_xf16 + (size_t)d * HS + q * 4);
    float2 huA = __half22float2(hu2[0]), huB = __half22float2(hu2[1]);
    float2 xfA = __half22float2(xf2[0]), xfB = __half22float2(xf2[1]);
    float* hs = g_hsum + (size_t)d * HS + q * 4;
    float* fc = g_fcsum + (size_t)d * HS + q * 4;
    atomicAdd(hs + 0, h4.x); atomicAdd(hs + 1, h4.y);
    atomicAdd(hs + 2, h4.z); atomicAdd(hs + 3, h4.w);
    atomicAdd(fc + 0, sigmoidf(xfA.x + huA.x) * c4.x);
    atomicAdd(fc + 1, sigmoidf(xfA.y + huA.y) * c4.y);
    atomicAdd(fc + 2, sigmoidf(xfB.x + huB.x) * c4.z);
    atomicAdd(fc + 3, sigmoidf(xfB.y + huB.y) * c4.w);
}

// ---------------- final node update (streaming, high occupancy) ----------------
__global__ void k_final(float* __restrict__ out) {
    int idx = blockIdx.x * blockDim.x + threadIdx.x;
    if (idx >= NN * HS) return;
    int n = idx >> 7;
    int j = idx & 127;
    size_t b = (size_t)n * 384;
    float i_ = sigmoidf(g_xall[b + j]       + g_uhsum[b + j]);
    float o_ = sigmoidf(g_xall[b + 128 + j] + g_uhsum[b + 128 + j]);
    float u_ = tanhf(   g_xall[b + 256 + j] + g_uhsum[b + 256 + j]);
    float c = i_ * u_ + g_fcsum[idx];
    float h = o_ * tanhf(c);
    out[idx] = h;
    out[(size_t)NN * HS + idx] = c;
}

// ============================================================================
extern "C" void kernel_launch(void* const* d_in, const int* in_sizes, int n_in,
                              void* d_out, int out_size) {
    const float* x       = (const float*)d_in[0];
    const float* h_child = (const float*)d_in[1];
    const float* c_child = (const float*)d_in[2];
    const float* w_iou   = (const float*)d_in[3];
    const float* b_iou   = (const float*)d_in[4];
    const float* w_f     = (const float*)d_in[5];
    const float* b_f     = (const float*)d_in[6];
    const float* u_iou   = (const float*)d_in[7];
    const float* u_f     = (const float*)d_in[8];
    const int*   esrc    = (const int*)d_in[9];
    const int*   edst    = (const int*)d_in[10];
    float* out = (float*)d_out;

    static bool configured = false;
    if (!configured) {
        cudaFuncSetAttribute(k_mma, cudaFuncAttributeMaxDynamicSharedMemorySize, SMEM_MMA);
        configured = true;
    }

    const int total4 = NN * HS / 4;
    const int sgrid = (total4 + 255) / 256;

    k_prep<<<131072 / 256, 256>>>(w_iou, w_f, u_iou, u_f, b_iou, b_f);
    k_split<<<sgrid, 256>>>(x, 0);            // also zeroes g_hsum/g_fcsum
    k_split<<<sgrid, 256>>>(h_child, 1);
    k_mma<<<ROW_TILES, 256, SMEM_MMA>>>(0);   // x -> g_xall (i|o|u) + g_xf16 (f)
    k_mma<<<ROW_TILES, 256, SMEM_MMA>>>(1);   // h_child -> g_hu16
    k_edge<<<(NE * 32) / 256, 256>>>(h_child, c_child, esrc, edst);
    k_split<<<sgrid, 256>>>(nullptr, 2);      // g_hsum -> g_shi/g_slo
    k_mma<<<ROW_TILES, 256, SMEM_MMA>>>(2);   // g_hsum -> g_uhsum
    k_final<<<(NN * HS + 255) / 256, 256>>>(out);
}